// round 6
// baseline (speedup 1.0000x reference)
#include <cuda_runtime.h>
#include <cuda_bf16.h>

#define N_COLS 2048                 // hidden dim
#define VECS_PER_ROW (N_COLS / 4)   // 512 float4
#define THREADS 256                 // 2 float4 per thread per row
#define EPS 1e-5f

__global__ __launch_bounds__(THREADS)
void rmsnorm_persistent_kernel(const float4* __restrict__ x,
                               const float4* __restrict__ g,
                               float4* __restrict__ out,
                               int n_rows)
{
    const int t = threadIdx.x;
    const int warp = t >> 5;
    const int lane = t & 31;

    __shared__ float warp_sums[THREADS / 32];
    __shared__ float s_scale;

    // g is tiny (8 KB) and reused for every row: load once into registers.
    const float4 g0 = g[t];
    const float4 g1 = g[t + THREADS];

    int row = blockIdx.x;
    const int stride = gridDim.x;

    // Prologue: load first row.
    float4 c0, c1;
    {
        const float4* xr = x + (size_t)row * VECS_PER_ROW;
        c0 = xr[t];
        c1 = xr[t + THREADS];
    }

    while (row < n_rows) {
        const int next = row + stride;

        // Issue next row's loads BEFORE the reduce barriers/stores so reads
        // stay in flight through the current row's compute+store phase.
        float4 n0 = make_float4(0.f, 0.f, 0.f, 0.f);
        float4 n1 = make_float4(0.f, 0.f, 0.f, 0.f);
        if (next < n_rows) {
            const float4* xn = x + (size_t)next * VECS_PER_ROW;
            n0 = xn[t];
            n1 = xn[t + THREADS];
        }

        // Sum of squares for current row.
        float ss = c0.x * c0.x + c0.y * c0.y + c0.z * c0.z + c0.w * c0.w
                 + c1.x * c1.x + c1.y * c1.y + c1.z * c1.z + c1.w * c1.w;

        #pragma unroll
        for (int off = 16; off > 0; off >>= 1)
            ss += __shfl_xor_sync(0xFFFFFFFFu, ss, off);

        if (lane == 0) warp_sums[warp] = ss;
        __syncthreads();
        if (warp == 0) {
            float s = (lane < THREADS / 32) ? warp_sums[lane] : 0.0f;
            #pragma unroll
            for (int off = 4; off > 0; off >>= 1)
                s += __shfl_xor_sync(0xFFFFFFFFu, s, off);
            if (lane == 0)
                s_scale = rsqrtf(s * (1.0f / (float)N_COLS) + EPS);
        }
        __syncthreads();
        const float scale = s_scale;
        __syncthreads();   // protect s_scale/warp_sums before next iteration overwrites

        float4* outr = out + (size_t)row * VECS_PER_ROW;
        float4 o0, o1;
        o0.x = c0.x * scale * g0.x;
        o0.y = c0.y * scale * g0.y;
        o0.z = c0.z * scale * g0.z;
        o0.w = c0.w * scale * g0.w;
        o1.x = c1.x * scale * g1.x;
        o1.y = c1.y * scale * g1.y;
        o1.z = c1.z * scale * g1.z;
        o1.w = c1.w * scale * g1.w;
        outr[t] = o0;
        outr[t + THREADS] = o1;

        c0 = n0;
        c1 = n1;
        row = next;
    }
}

extern "C" void kernel_launch(void* const* d_in, const int* in_sizes, int n_in,
                              void* d_out, int out_size)
{
    const float4* x = (const float4*)d_in[0];
    const float4* g = (const float4*)d_in[1];
    float4* out = (float4*)d_out;

    const int n_rows = in_sizes[0] / N_COLS;  // 16384

    // Size the persistent grid to exactly one resident wave.
    // Host-side queries run at capture time only — free during replay.
    int dev = 0, sms = 148, blocks_per_sm = 0;
    cudaGetDevice(&dev);
    cudaDeviceGetAttribute(&sms, cudaDevAttrMultiProcessorCount, dev);
    cudaOccupancyMaxActiveBlocksPerMultiprocessor(
        &blocks_per_sm, rmsnorm_persistent_kernel, THREADS, 0);
    if (blocks_per_sm < 1) blocks_per_sm = 1;

    int grid = sms * blocks_per_sm;
    if (grid > n_rows) grid = n_rows;

    rmsnorm_persistent_kernel<<<grid, THREADS>>>(x, g, out, n_rows);
}

// round 7
// speedup vs baseline: 1.0934x; 1.0934x over previous
#include <cuda_runtime.h>
#include <cuda_bf16.h>

#define N_COLS 2048                 // hidden dim
#define VECS_PER_ROW (N_COLS / 4)   // 512 float4
#define THREADS 256                 // 2 float4 per thread
#define NWARPS (THREADS / 32)
#define EPS 1e-5f

__global__ __launch_bounds__(THREADS)
void rmsnorm_kernel(const float4* __restrict__ x,
                    const float4* __restrict__ g,
                    float4* __restrict__ out)
{
    const int row = blockIdx.x;
    const float4* xr = x + (size_t)row * VECS_PER_ROW;
    float4* outr = out + (size_t)row * VECS_PER_ROW;

    const int t = threadIdx.x;
    const int warp = t >> 5;
    const int lane = t & 31;

    // x has zero reuse within a launch: bypass L1 fill (L2-only).
    float4 v0 = __ldcg(&xr[t]);
    float4 v1 = __ldcg(&xr[t + THREADS]);

    float ss = v0.x * v0.x + v0.y * v0.y + v0.z * v0.z + v0.w * v0.w
             + v1.x * v1.x + v1.y * v1.y + v1.z * v1.z + v1.w * v1.w;

    // Warp reduce.
    #pragma unroll
    for (int off = 16; off > 0; off >>= 1)
        ss += __shfl_xor_sync(0xFFFFFFFFu, ss, off);

    // Single-barrier block reduce: publish 8 warp partials, then every
    // thread sums all 8 from smem (broadcast reads, no second barrier,
    // no serialized warp0 chain).
    __shared__ float warp_sums[NWARPS];
    if (lane == 0) warp_sums[warp] = ss;
    __syncthreads();

    float total = 0.0f;
    #pragma unroll
    for (int w = 0; w < NWARPS; w++)
        total += warp_sums[w];

    const float scale = rsqrtf(total * (1.0f / (float)N_COLS) + EPS);

    // g: 8 KB, broadcast across all rows — default policy, L1/L2-resident.
    float4 g0 = g[t];
    float4 g1 = g[t + THREADS];

    float4 o0, o1;
    o0.x = v0.x * scale * g0.x;
    o0.y = v0.y * scale * g0.y;
    o0.z = v0.z * scale * g0.z;
    o0.w = v0.w * scale * g0.w;
    o1.x = v1.x * scale * g1.x;
    o1.y = v1.y * scale * g1.y;
    o1.z = v1.z * scale * g1.z;
    o1.w = v1.w * scale * g1.w;

    outr[t] = o0;
    outr[t + THREADS] = o1;
}

extern "C" void kernel_launch(void* const* d_in, const int* in_sizes, int n_in,
                              void* d_out, int out_size)
{
    const float4* x = (const float4*)d_in[0];
    const float4* g = (const float4*)d_in[1];
    float4* out = (float4*)d_out;

    const int n_rows = in_sizes[0] / N_COLS;  // 16384

    rmsnorm_kernel<<<n_rows, THREADS>>>(x, g, out);
}

// round 9
// speedup vs baseline: 1.0942x; 1.0007x over previous
#include <cuda_runtime.h>
#include <cuda_bf16.h>

#define N_COLS 2048                 // hidden dim
#define VECS_PER_ROW (N_COLS / 4)   // 512 float4
#define THREADS 256                 // 2 float4 per thread
#define NWARPS (THREADS / 32)
#define EPS 1e-5f

__global__ __launch_bounds__(THREADS)
void rmsnorm_kernel(const float4* __restrict__ x,
                    const float4* __restrict__ g,
                    float4* __restrict__ out)
{
    const int row = blockIdx.x;
    const float4* xr = x + (size_t)row * VECS_PER_ROW;
    float4* outr = out + (size_t)row * VECS_PER_ROW;

    const int t = threadIdx.x;
    const int warp = t >> 5;
    const int lane = t & 31;

    // x has zero reuse within a launch: bypass L1 fill (L2-only).
    float4 v0 = __ldcg(&xr[t]);
    float4 v1 = __ldcg(&xr[t + THREADS]);

    // g: 8 KB, broadcast across all rows, L1/L2-resident. Issue BEFORE the
    // reduce/barrier so its latency overlaps the shuffle tree + BAR wait
    // instead of sitting on the post-reduce critical path.
    float4 g0 = g[t];
    float4 g1 = g[t + THREADS];

    float ss = v0.x * v0.x + v0.y * v0.y + v0.z * v0.z + v0.w * v0.w
             + v1.x * v1.x + v1.y * v1.y + v1.z * v1.z + v1.w * v1.w;

    // Warp reduce (redux.sync.add.f32 is NOT supported on sm_103).
    #pragma unroll
    for (int off = 16; off > 0; off >>= 1)
        ss += __shfl_xor_sync(0xFFFFFFFFu, ss, off);

    // Single-barrier block reduce: publish 8 warp partials, every thread
    // sums all 8 from smem (broadcast LDS, no second barrier).
    __shared__ float warp_sums[NWARPS];
    if (lane == 0) warp_sums[warp] = ss;
    __syncthreads();

    float total = 0.0f;
    #pragma unroll
    for (int w = 0; w < NWARPS; w++)
        total += warp_sums[w];

    const float scale = rsqrtf(total * (1.0f / (float)N_COLS) + EPS);

    float4 o0, o1;
    o0.x = v0.x * scale * g0.x;
    o0.y = v0.y * scale * g0.y;
    o0.z = v0.z * scale * g0.z;
    o0.w = v0.w * scale * g0.w;
    o1.x = v1.x * scale * g1.x;
    o1.y = v1.y * scale * g1.y;
    o1.z = v1.z * scale * g1.z;
    o1.w = v1.w * scale * g1.w;

    outr[t] = o0;
    outr[t + THREADS] = o1;
}

extern "C" void kernel_launch(void* const* d_in, const int* in_sizes, int n_in,
                              void* d_out, int out_size)
{
    const float4* x = (const float4*)d_in[0];
    const float4* g = (const float4*)d_in[1];
    float4* out = (float4*)d_out;

    const int n_rows = in_sizes[0] / N_COLS;  // 16384

    rmsnorm_kernel<<<n_rows, THREADS>>>(x, g, out);
}